// round 3
// baseline (speedup 1.0000x reference)
#include <cuda_runtime.h>

#define QF 64
#define PTS_PER_WARP 288   // multiple of 4; 6945 warps -> single wave @ 12 blocks/SM

typedef unsigned long long ull;

__global__ void perslay_zero_kernel(float4* __restrict__ out, int n4) {
    int i = blockIdx.x * blockDim.x + threadIdx.x;
    if (i < n4) out[i] = make_float4(0.f, 0.f, 0.f, 0.f);
}

__device__ __forceinline__ float ex2_approx(float x) {
    float r;
    asm("ex2.approx.f32 %0, %1;" : "=f"(r) : "f"(x));
    return r;
}
__device__ __forceinline__ ull pack2(float lo, float hi) {
    ull r;
    asm("mov.b64 %0, {%1, %2};" : "=l"(r) : "f"(lo), "f"(hi));
    return r;
}
__device__ __forceinline__ void unpack2(ull v, float& lo, float& hi) {
    asm("mov.b64 {%0, %1}, %2;" : "=f"(lo), "=f"(hi) : "l"(v));
}
__device__ __forceinline__ ull fma2(ull a, ull b, ull c) {
    ull d;
    asm("fma.rn.f32x2 %0, %1, %2, %3;" : "=l"(d) : "l"(a), "l"(b), "l"(c));
    return d;
}
__device__ __forceinline__ ull mul2(ull a, ull b) {
    ull d;
    asm("mul.rn.f32x2 %0, %1, %2;" : "=l"(d) : "l"(a), "l"(b));
    return d;
}

// Per (point, q): z=(zx,zy) packed over DIMENSIONS (coords arrive as an
// aligned register pair from the vector load -> zero packing MOVs).
//   z  = p*a + b          (1 FFMA2)   a=(ax,ay)*sqrt(log2 e), b=-(px,py)*a
//   z2 = z*z              (1 FMUL2)
//   t  = -z2.lo - z2.hi   (1 FADD, negate modifiers free)
//   acc += ex2(t)         (1 MUFU + 1 FADD)
__device__ __forceinline__ void gq(ull p, ull a, ull b, float& acc) {
    const ull z  = fma2(p, a, b);
    const ull z2 = mul2(z, z);
    float lo, hi;
    unpack2(z2, lo, hi);
    const float t = -lo - hi;
    acc += ex2_approx(t);
}

__device__ __forceinline__ void flush(float* __restrict__ out, int cur, int q0,
                                      float& a0, float& a1)
{
    atomicAdd(&out[cur * QF + q0],     a0);
    atomicAdd(&out[cur * QF + q0 + 1], a1);
    a0 = 0.f;
    a1 = 0.f;
}

// One warp handles a contiguous run of points and all Q=64 features
// (lane l owns q=2l, 2l+1). Sorted point_index -> register accumulation,
// atomic flush only at segment boundaries (~1.6 per warp total).
__global__ __launch_bounds__(128) void perslay_kernel(
    const float2* __restrict__ xy,
    const int*    __restrict__ seg,
    const float*  __restrict__ sp,
    const float*  __restrict__ isg,
    float*        __restrict__ out,
    int n)
{
    const int warp_id = blockIdx.x * (blockDim.x >> 5) + (threadIdx.x >> 5);
    const int lane    = threadIdx.x & 31;
    const int start   = warp_id * PTS_PER_WARP;
    if (start >= n) return;
    const int end = min(start + PTS_PER_WARP, n);

    const int q0 = 2 * lane;
    const int q1 = q0 + 1;

    // sqrt(log2 e) folded into sigma scale: exp(-d2) == ex2(-(scaled d2)).
    const float SL  = 1.2011224087864498f;
    const float ax0 = isg[q0]      * SL, ax1 = isg[q1]      * SL;
    const float ay0 = isg[QF + q0] * SL, ay1 = isg[QF + q1] * SL;
    const float bx0 = -sp[q0]      * ax0, bx1 = -sp[q1]      * ax1;
    const float by0 = -sp[QF + q0] * ay0, by1 = -sp[QF + q1] * ay1;

    const ull a0 = pack2(ax0, ay0);   // loop-invariant packs
    const ull b0 = pack2(bx0, by0);
    const ull a1 = pack2(ax1, ay1);
    const ull b1 = pack2(bx1, by1);

    const float4* __restrict__ xy4 = (const float4*)xy;  // 2 points per float4

    float acc0 = 0.f, acc1 = 0.f;
    int cur = seg[start];

    int p = start;
    for (; p + 4 <= end; p += 4) {
        const float4 c01 = xy4[p >> 1];
        const float4 c23 = xy4[(p >> 1) + 1];
        const int4   s   = *reinterpret_cast<const int4*>(seg + p);
        // (x,y) pairs are aligned register pairs straight from LDG.128.
        const ull p0 = pack2(c01.x, c01.y);
        const ull p1 = pack2(c01.z, c01.w);
        const ull p2 = pack2(c23.x, c23.y);
        const ull p3 = pack2(c23.z, c23.w);
        if (s.w == cur) {
            // sorted & s.w == cur  =>  whole chunk in segment 'cur'
            gq(p0, a0, b0, acc0);  gq(p0, a1, b1, acc1);
            gq(p1, a0, b0, acc0);  gq(p1, a1, b1, acc1);
            gq(p2, a0, b0, acc0);  gq(p2, a1, b1, acc1);
            gq(p3, a0, b0, acc0);  gq(p3, a1, b1, acc1);
        } else {
            if (s.x != cur) { flush(out, cur, q0, acc0, acc1); cur = s.x; }
            gq(p0, a0, b0, acc0);  gq(p0, a1, b1, acc1);
            if (s.y != cur) { flush(out, cur, q0, acc0, acc1); cur = s.y; }
            gq(p1, a0, b0, acc0);  gq(p1, a1, b1, acc1);
            if (s.z != cur) { flush(out, cur, q0, acc0, acc1); cur = s.z; }
            gq(p2, a0, b0, acc0);  gq(p2, a1, b1, acc1);
            if (s.w != cur) { flush(out, cur, q0, acc0, acc1); cur = s.w; }
            gq(p3, a0, b0, acc0);  gq(p3, a1, b1, acc1);
        }
    }
    for (; p < end; ++p) {  // tail (< 4 points)
        const float2 c = xy[p];
        const int    sv = seg[p];
        if (sv != cur) { flush(out, cur, q0, acc0, acc1); cur = sv; }
        const ull pp = pack2(c.x, c.y);
        gq(pp, a0, b0, acc0);
        gq(pp, a1, b1, acc1);
    }
    flush(out, cur, q0, acc0, acc1);
}

extern "C" void kernel_launch(void* const* d_in, const int* in_sizes, int n_in,
                              void* d_out, int out_size) {
    const float2* xy  = (const float2*)d_in[0];
    const int*    seg = (const int*)   d_in[1];
    const float*  sp  = (const float*) d_in[2];
    const float*  isg = (const float*) d_in[3];
    float*        out = (float*)d_out;

    const int n = in_sizes[0] / 2;   // input is [N,2] float32

    const int n4 = out_size >> 2;    // 4096*64 / 4
    perslay_zero_kernel<<<(n4 + 255) / 256, 256>>>((float4*)out, n4);

    const int num_warps = (n + PTS_PER_WARP - 1) / PTS_PER_WARP;
    const int blocks    = (num_warps + 3) / 4;   // 4 warps / block
    perslay_kernel<<<blocks, 128>>>(xy, seg, sp, isg, out, n);
}

// round 4
// speedup vs baseline: 1.0695x; 1.0695x over previous
#include <cuda_runtime.h>

#define QF 64
#define PTS_PER_WARP 256   // multiple of 8; 7813 warps ≈ 53 warps/SM, one wave

__global__ void perslay_zero_kernel(float4* __restrict__ out, int n4) {
    int i = blockIdx.x * blockDim.x + threadIdx.x;
    if (i < n4) out[i] = make_float4(0.f, 0.f, 0.f, 0.f);
}

__device__ __forceinline__ float ex2_approx(float x) {
    float r;
    asm("ex2.approx.f32 %0, %1;" : "=f"(r) : "f"(x));
    return r;
}

// phi(x,y) for one q via pure-FFMA quadratic chain (no MOVs, no extra FADD):
//   t = ((A*x + B)*x + C) + (Ay*y + By)*y      == -(ax(x-px))^2-(ay(y-py))^2, log2 units
//   4 FFMA -> 1 MUFU -> 1 FADD(acc)
__device__ __forceinline__ float gq(float x, float y,
                                    float A, float B, float C,
                                    float Ay, float By)
{
    const float u = fmaf(x, A, B);
    const float v = fmaf(x, u, C);
    const float w = fmaf(y, Ay, By);
    const float t = fmaf(y, w, v);
    return ex2_approx(t);
}

__global__ __launch_bounds__(256) void perslay_kernel(
    const float2* __restrict__ xy,
    const int*    __restrict__ seg,
    const float*  __restrict__ sp,
    const float*  __restrict__ isg,
    float*        __restrict__ out,
    int n)
{
    const int warp_id = blockIdx.x * (blockDim.x >> 5) + (threadIdx.x >> 5);
    const int lane    = threadIdx.x & 31;
    const int start   = warp_id * PTS_PER_WARP;
    if (start >= n) return;
    const int end = min(start + PTS_PER_WARP, n);

    const int q0 = 2 * lane;
    const int q1 = q0 + 1;

    // sqrt(log2 e) folded into sigma scale so a bare ex2 replaces exp.
    const float SL  = 1.2011224087864498f;
    const float px0 = sp[q0],      px1 = sp[q1];
    const float py0 = sp[QF + q0], py1 = sp[QF + q1];
    const float ax0 = isg[q0]      * SL, ax1 = isg[q1]      * SL;
    const float ay0 = isg[QF + q0] * SL, ay1 = isg[QF + q1] * SL;

    const float A0  = -ax0 * ax0,       A1  = -ax1 * ax1;
    const float Ay0 = -ay0 * ay0,       Ay1 = -ay1 * ay1;
    const float B0  = -2.f * A0  * px0, B1  = -2.f * A1  * px1;
    const float By0 = -2.f * Ay0 * py0, By1 = -2.f * Ay1 * py1;
    const float C0  = A0 * px0 * px0 + Ay0 * py0 * py0;
    const float C1  = A1 * px1 * px1 + Ay1 * py1 * py1;

    const float4* __restrict__ xy4 = (const float4*)xy;   // 2 points / float4

    // Two accumulators per q break the serial FADD-acc chain.
    float a0a = 0.f, a0b = 0.f, a1a = 0.f, a1b = 0.f;
    int cur = seg[start];

    #define FLUSH() do {                                                   \
        atomicAdd(&out[cur * QF + q0], a0a + a0b);                         \
        atomicAdd(&out[cur * QF + q1], a1a + a1b);                         \
        a0a = 0.f; a0b = 0.f; a1a = 0.f; a1b = 0.f;                        \
    } while (0)

    #define POINT_A(X, Y) do {                                             \
        a0a += gq((X), (Y), A0, B0, C0, Ay0, By0);                         \
        a1a += gq((X), (Y), A1, B1, C1, Ay1, By1);                         \
    } while (0)
    #define POINT_B(X, Y) do {                                             \
        a0b += gq((X), (Y), A0, B0, C0, Ay0, By0);                         \
        a1b += gq((X), (Y), A1, B1, C1, Ay1, By1);                         \
    } while (0)

    int p = start;
    for (; p + 8 <= end; p += 8) {
        const float4 c01 = xy4[(p >> 1) + 0];
        const float4 c23 = xy4[(p >> 1) + 1];
        const float4 c45 = xy4[(p >> 1) + 2];
        const float4 c67 = xy4[(p >> 1) + 3];
        const int4   sLo = *reinterpret_cast<const int4*>(seg + p);
        const int4   sHi = *reinterpret_cast<const int4*>(seg + p + 4);
        if (sHi.w == cur) {
            // sorted & last == cur  =>  whole 8-chunk belongs to 'cur'
            POINT_A(c01.x, c01.y);  POINT_B(c01.z, c01.w);
            POINT_A(c23.x, c23.y);  POINT_B(c23.z, c23.w);
            POINT_A(c45.x, c45.y);  POINT_B(c45.z, c45.w);
            POINT_A(c67.x, c67.y);  POINT_B(c67.z, c67.w);
        } else {
            if (sLo.x != cur) { FLUSH(); cur = sLo.x; }
            POINT_A(c01.x, c01.y);
            if (sLo.y != cur) { FLUSH(); cur = sLo.y; }
            POINT_B(c01.z, c01.w);
            if (sLo.z != cur) { FLUSH(); cur = sLo.z; }
            POINT_A(c23.x, c23.y);
            if (sLo.w != cur) { FLUSH(); cur = sLo.w; }
            POINT_B(c23.z, c23.w);
            if (sHi.x != cur) { FLUSH(); cur = sHi.x; }
            POINT_A(c45.x, c45.y);
            if (sHi.y != cur) { FLUSH(); cur = sHi.y; }
            POINT_B(c45.z, c45.w);
            if (sHi.z != cur) { FLUSH(); cur = sHi.z; }
            POINT_A(c67.x, c67.y);
            if (sHi.w != cur) { FLUSH(); cur = sHi.w; }
            POINT_B(c67.z, c67.w);
        }
    }
    for (; p < end; ++p) {   // tail (< 8 points)
        const float2 c  = xy[p];
        const int    sv = seg[p];
        if (sv != cur) { FLUSH(); cur = sv; }
        POINT_A(c.x, c.y);
    }
    FLUSH();

    #undef FLUSH
    #undef POINT_A
    #undef POINT_B
}

extern "C" void kernel_launch(void* const* d_in, const int* in_sizes, int n_in,
                              void* d_out, int out_size) {
    const float2* xy  = (const float2*)d_in[0];
    const int*    seg = (const int*)   d_in[1];
    const float*  sp  = (const float*) d_in[2];
    const float*  isg = (const float*) d_in[3];
    float*        out = (float*)d_out;

    const int n = in_sizes[0] / 2;   // input is [N,2] float32

    const int n4 = out_size >> 2;    // 4096*64 / 4
    perslay_zero_kernel<<<(n4 + 255) / 256, 256>>>((float4*)out, n4);

    const int num_warps = (n + PTS_PER_WARP - 1) / PTS_PER_WARP;
    const int blocks    = (num_warps + 7) / 8;   // 8 warps / block
    perslay_kernel<<<blocks, 256>>>(xy, seg, sp, isg, out, n);
}

// round 6
// speedup vs baseline: 1.1071x; 1.0352x over previous
#include <cuda_runtime.h>

#define QF 64
#define PTS_PER_WARP 344   // multiple of 8; 5814 warps -> 727 blocks (<740) = ONE wave

__global__ void perslay_zero_kernel(float4* __restrict__ out, int n4) {
    int i = blockIdx.x * blockDim.x + threadIdx.x;
    if (i < n4) out[i] = make_float4(0.f, 0.f, 0.f, 0.f);
}

__device__ __forceinline__ float ex2_approx(float x) {
    float r;
    asm("ex2.approx.f32 %0, %1;" : "=f"(r) : "f"(x));
    return r;
}

// phi(x,y) for one q via pure-FFMA quadratic chain:
//   t = ((A*x + B)*x + C) + (Ay*y + By)*y   == -(ax(x-px))^2-(ay(y-py))^2 in log2 units
//   4 FFMA -> 1 MUFU -> 1 FADD(acc)
__device__ __forceinline__ float gq(float x, float y,
                                    float A, float B, float C,
                                    float Ay, float By)
{
    const float u = fmaf(x, A, B);
    const float v = fmaf(x, u, C);
    const float w = fmaf(y, Ay, By);
    const float t = fmaf(y, w, v);
    return ex2_approx(t);
}

__global__ __launch_bounds__(256, 5) void perslay_kernel(
    const float2* __restrict__ xy,
    const int*    __restrict__ seg,
    const float*  __restrict__ sp,
    const float*  __restrict__ isg,
    float*        __restrict__ out,
    int n)
{
    const int warp_id = blockIdx.x * (blockDim.x >> 5) + (threadIdx.x >> 5);
    const int lane    = threadIdx.x & 31;
    const int start   = warp_id * PTS_PER_WARP;
    if (start >= n) return;
    const int end = min(start + PTS_PER_WARP, n);

    const int q0 = 2 * lane;
    const int q1 = q0 + 1;

    // sqrt(log2 e) folded into sigma scale so a bare ex2 replaces exp.
    const float SL  = 1.2011224087864498f;
    const float px0 = sp[q0],      px1 = sp[q1];
    const float py0 = sp[QF + q0], py1 = sp[QF + q1];
    const float ax0 = isg[q0]      * SL, ax1 = isg[q1]      * SL;
    const float ay0 = isg[QF + q0] * SL, ay1 = isg[QF + q1] * SL;

    const float A0  = -ax0 * ax0,       A1  = -ax1 * ax1;
    const float Ay0 = -ay0 * ay0,       Ay1 = -ay1 * ay1;
    const float B0  = -2.f * A0  * px0, B1  = -2.f * A1  * px1;
    const float By0 = -2.f * Ay0 * py0, By1 = -2.f * Ay1 * py1;
    const float C0  = A0 * px0 * px0 + Ay0 * py0 * py0;
    const float C1  = A1 * px1 * px1 + Ay1 * py1 * py1;

    // Advancing pointers: no per-iteration indexed address IMADs.
    const float4* __restrict__ cp  = (const float4*)(xy + start);
    const int4*   __restrict__ sp4 = (const int4*)(seg + start);

    // Two accumulators per q break the serial FADD-acc chain.
    float a0a = 0.f, a0b = 0.f, a1a = 0.f, a1b = 0.f;
    int cur = seg[start];

    #define FLUSH() do {                                                   \
        atomicAdd(&out[cur * QF + q0], a0a + a0b);                         \
        atomicAdd(&out[cur * QF + q1], a1a + a1b);                         \
        a0a = 0.f; a0b = 0.f; a1a = 0.f; a1b = 0.f;                        \
    } while (0)

    #define POINT_A(X, Y) do {                                             \
        a0a += gq((X), (Y), A0, B0, C0, Ay0, By0);                         \
        a1a += gq((X), (Y), A1, B1, C1, Ay1, By1);                         \
    } while (0)
    #define POINT_B(X, Y) do {                                             \
        a0b += gq((X), (Y), A0, B0, C0, Ay0, By0);                         \
        a1b += gq((X), (Y), A1, B1, C1, Ay1, By1);                         \
    } while (0)

    int p = start;
    for (; p + 8 <= end; p += 8, cp += 4, sp4 += 2) {
        const float4 c01 = cp[0];
        const float4 c23 = cp[1];
        const float4 c45 = cp[2];
        const float4 c67 = cp[3];
        const int4   sLo = sp4[0];
        const int4   sHi = sp4[1];
        if (sHi.w == cur) {
            // sorted & last == cur  =>  whole 8-chunk belongs to 'cur'
            POINT_A(c01.x, c01.y);  POINT_B(c01.z, c01.w);
            POINT_A(c23.x, c23.y);  POINT_B(c23.z, c23.w);
            POINT_A(c45.x, c45.y);  POINT_B(c45.z, c45.w);
            POINT_A(c67.x, c67.y);  POINT_B(c67.z, c67.w);
        } else {
            if (sLo.x != cur) { FLUSH(); cur = sLo.x; }
            POINT_A(c01.x, c01.y);
            if (sLo.y != cur) { FLUSH(); cur = sLo.y; }
            POINT_B(c01.z, c01.w);
            if (sLo.z != cur) { FLUSH(); cur = sLo.z; }
            POINT_A(c23.x, c23.y);
            if (sLo.w != cur) { FLUSH(); cur = sLo.w; }
            POINT_B(c23.z, c23.w);
            if (sHi.x != cur) { FLUSH(); cur = sHi.x; }
            POINT_A(c45.x, c45.y);
            if (sHi.y != cur) { FLUSH(); cur = sHi.y; }
            POINT_B(c45.z, c45.w);
            if (sHi.z != cur) { FLUSH(); cur = sHi.z; }
            POINT_A(c67.x, c67.y);
            if (sHi.w != cur) { FLUSH(); cur = sHi.w; }
            POINT_B(c67.z, c67.w);
        }
    }
    for (; p < end; ++p) {   // tail (< 8 points)
        const float2 c  = xy[p];
        const int    sv = seg[p];
        if (sv != cur) { FLUSH(); cur = sv; }
        POINT_A(c.x, c.y);
    }
    FLUSH();

    #undef FLUSH
    #undef POINT_A
    #undef POINT_B
}

extern "C" void kernel_launch(void* const* d_in, const int* in_sizes, int n_in,
                              void* d_out, int out_size) {
    const float2* xy  = (const float2*)d_in[0];
    const int*    seg = (const int*)   d_in[1];
    const float*  sp  = (const float*) d_in[2];
    const float*  isg = (const float*) d_in[3];
    float*        out = (float*)d_out;

    const int n = in_sizes[0] / 2;   // input is [N,2] float32

    const int n4 = out_size >> 2;    // 4096*64 / 4
    perslay_zero_kernel<<<(n4 + 255) / 256, 256>>>((float4*)out, n4);

    const int num_warps = (n + PTS_PER_WARP - 1) / PTS_PER_WARP;
    const int blocks    = (num_warps + 7) / 8;   // 8 warps / block
    perslay_kernel<<<blocks, 256>>>(xy, seg, sp, isg, out, n);
}